// round 2
// baseline (speedup 1.0000x reference)
#include <cuda_runtime.h>

// Problem constants (from reference setup_inputs)
constexpr int B = 2;
constexpr int D = 160;
constexpr int H = 192;
constexpr int W = 160;
constexpr int HW = H * W;            // 30720
constexpr int N = D * H * W;         // 4,915,200 voxels per batch

__global__ __launch_bounds__(256)
void warp3d_scalar_kernel(const float* __restrict__ src,
                          const float* __restrict__ flow,
                          float* __restrict__ out) {
    int tid = blockIdx.x * blockDim.x + threadIdx.x;
    constexpr int total = B * N;
    if (tid >= total) return;

    int b = tid / N;
    int r = tid - b * N;           // voxel index within batch
    int d = r / HW;
    int hw = r - d * HW;
    int h = hw / W;
    int w = hw - h * W;

    const float* fbase = flow + (size_t)b * 3 * N + r;
    float fz = __ldg(fbase);
    float fy = __ldg(fbase + N);
    float fx = __ldg(fbase + 2 * N);

    // coord = (id + flow) * S/(S-1) - 0.5
    constexpr float sz = (float)D / (float)(D - 1);
    constexpr float sy = (float)H / (float)(H - 1);
    constexpr float sx = (float)W / (float)(W - 1);

    float z = fmaf((float)d + fz, sz, -0.5f);
    float y = fmaf((float)h + fy, sy, -0.5f);
    float x = fmaf((float)w + fx, sx, -0.5f);

    float z0f = floorf(z), y0f = floorf(y), x0f = floorf(x);
    int z0 = (int)z0f, y0 = (int)y0f, x0 = (int)x0f;
    float wz1 = z - z0f, wy1 = y - y0f, wx1 = x - x0f;
    float wz0 = 1.0f - wz1, wy0 = 1.0f - wy1, wx0 = 1.0f - wx1;

    const float* s = src + (size_t)b * N;

    // in-bounds predicates via unsigned compares
    bool z0in = (unsigned)z0 < (unsigned)D;
    bool z1in = (unsigned)(z0 + 1) < (unsigned)D;
    bool y0in = (unsigned)y0 < (unsigned)H;
    bool y1in = (unsigned)(y0 + 1) < (unsigned)H;
    bool x0in = (unsigned)x0 < (unsigned)W;
    bool x1in = (unsigned)(x0 + 1) < (unsigned)W;

    int base00 = z0 * HW + y0 * W + x0;       // (z0,y0,x0)
    int base01 = base00 + W;                  // (z0,y1,x0)
    int base10 = base00 + HW;                 // (z1,y0,x0)
    int base11 = base10 + W;                  // (z1,y1,x0)

    float v000 = 0.f, v001 = 0.f, v010 = 0.f, v011 = 0.f;
    float v100 = 0.f, v101 = 0.f, v110 = 0.f, v111 = 0.f;

    if (z0in & y0in & x0in) v000 = __ldg(s + base00);
    if (z0in & y0in & x1in) v001 = __ldg(s + base00 + 1);
    if (z0in & y1in & x0in) v010 = __ldg(s + base01);
    if (z0in & y1in & x1in) v011 = __ldg(s + base01 + 1);
    if (z1in & y0in & x0in) v100 = __ldg(s + base10);
    if (z1in & y0in & x1in) v101 = __ldg(s + base10 + 1);
    if (z1in & y1in & x0in) v110 = __ldg(s + base11);
    if (z1in & y1in & x1in) v111 = __ldg(s + base11 + 1);

    // x-lerp, then y-lerp, then z-lerp (matches weight products exactly)
    float c00 = v000 * wx0 + v001 * wx1;
    float c01 = v010 * wx0 + v011 * wx1;
    float c10 = v100 * wx0 + v101 * wx1;
    float c11 = v110 * wx0 + v111 * wx1;

    float c0 = c00 * wy0 + c01 * wy1;
    float c1 = c10 * wy0 + c11 * wy1;

    out[tid] = c0 * wz0 + c1 * wz1;
}

extern "C" void kernel_launch(void* const* d_in, const int* in_sizes, int n_in,
                              void* d_out, int out_size) {
    const float* src = (const float*)d_in[0];
    const float* flow = (const float*)d_in[1];
    float* out = (float*)d_out;

    constexpr int total = B * N;             // 9,830,400
    constexpr int threads = 256;
    constexpr int blocks = (total + threads - 1) / threads;
    warp3d_scalar_kernel<<<blocks, threads>>>(src, flow, out);
}